// round 12
// baseline (speedup 1.0000x reference)
#include <cuda_runtime.h>
#include <cuda_bf16.h>

// ---------------------------------------------------------------------------
// EdgeNorm (one-pass moments), 4 lanes per edge (H==8), lane k owns heads
// {2k,2k+1}. float2 unit index == global thread-unit id (fully coalesced).
//
// Count elimination: lane 0 accumulates (x0 + CBIAS); count recovered in
// stats via rint(s.x/CBIAS). 4 LTS atomic ops per edge = structural floor.
//
// Scratch lifecycle (3 launches, no zero kernel):
//   accum8: RED.128 moments into g_acc (starts zeroed).
//   stats8: reads g_acc, writes (scale,offset) to g_so (resident stores),
//           zeroes g_acc with __stcs (evict-first: dead lines leave L2
//           immediately, preserving apply's es residency). Replay-safe.
//   apply8: gathers g_so; es re-read is L2-hit (working set
//           es 102.4 + dst 12.8 + g_so 8.4 = 123.6MB < 126MB L2);
//           output via __stcs so stores don't displace resident es;
//           reversed block order to start on accum's tail-hot lines.
// ---------------------------------------------------------------------------

#define MAX_NODES 131072
#define NTHREADS  256
#define UNITS     4
#define AUNITS    8
#define CBIAS     128.0f
#define CBIAS_INV (1.0f / 128.0f)

__device__ float4 g_acc[MAX_NODES * 4];   // moments (always zeroed after stats)
__device__ float  g_cnt[MAX_NODES];       // fallback path only
__device__ float4 g_so [MAX_NODES * 4];   // (scale,off,scale,off) per head-pair

// -------- H == 8 fast path -------------------------------------------------
__global__ void accum8_kernel(const float2* __restrict__ es2,
                              const int*    __restrict__ dst, int T)
{
    int base = blockIdx.x * (NTHREADS * UNITS) + threadIdx.x;
    int t[UNITS];
    bool ok[UNITS];
    int d[UNITS];
    float2 x[UNITS];
#pragma unroll
    for (int u = 0; u < UNITS; u++) {
        t[u] = base + u * NTHREADS;
        ok[u] = t[u] < T;
    }
#pragma unroll
    for (int u = 0; u < UNITS; u++)
        if (ok[u]) d[u] = dst[t[u] >> 2];
#pragma unroll
    for (int u = 0; u < UNITS; u++)
        if (ok[u]) x[u] = es2[t[u]];
#pragma unroll
    for (int u = 0; u < UNITS; u++) {
        if (ok[u]) {
            int k = t[u] & 3;
            float cb = (k == 0) ? CBIAS : 0.0f;   // count rides in lane 0's sum
            atomicAdd(&g_acc[d[u] * 4 + k],
                      make_float4(x[u].x + cb, x[u].x * x[u].x,
                                  x[u].y, x[u].y * x[u].y));
        }
    }
}

__global__ void stats8_kernel(const float* __restrict__ gain,
                              const float* __restrict__ bias)
{
    int t = blockIdx.x * blockDim.x + threadIdx.x;
    if (t >= MAX_NODES * 4) return;     // one thread per (node, head-pair)
    int k = t & 3;
    float4 s = g_acc[t];
    // zero own slot right after reading it (evict-first: don't hold L2 lines)
    float4 z = make_float4(0.f, 0.f, 0.f, 0.f);
    __stcs(&g_acc[t], z);

    // lane-0 slot of this node sits in lane (lane & ~3) of the same warp:
    // broadcast its raw sum (carries CBIAS*count) via shuffle, no 2nd load.
    int lane = threadIdx.x & 31;
    float s0x = __shfl_sync(0xffffffffu, s.x, lane & ~3);
    float c = rintf(s0x * CBIAS_INV);
    if (k == 0) s.x = s.x - CBIAS * c;

    float rinv = 1.0f / fmaxf(c, 1.0f);
    float m0 = s.x * rinv;
    float v0 = fmaxf(s.y - s.x * m0, 0.f) * rinv;
    float sc0 = gain[2 * k + 0] / fmaxf(sqrtf(v0), 1e-5f);
    float of0 = bias[2 * k + 0] - sc0 * m0;
    float m1 = s.z * rinv;
    float v1 = fmaxf(s.w - s.z * m1, 0.f) * rinv;
    float sc1 = gain[2 * k + 1] / fmaxf(sqrtf(v1), 1e-5f);
    float of1 = bias[2 * k + 1] - sc1 * m1;
    g_so[t] = make_float4(sc0, of0, sc1, of1);  // resident: apply gathers this
}

__global__ void apply8_kernel(const float2* __restrict__ es2,
                              const int*    __restrict__ dst,
                              float2*       __restrict__ out2, int T)
{
    // Reversed block order: read the es tail (still hot in L2 from accum) first.
    int rb = gridDim.x - 1 - blockIdx.x;
    int base = rb * (NTHREADS * AUNITS) + threadIdx.x;
    int t[AUNITS];
    bool ok[AUNITS];
    int d[AUNITS];
    float2 x[AUNITS];
    float4 s[AUNITS];
#pragma unroll
    for (int u = 0; u < AUNITS; u++) {
        t[u] = base + u * NTHREADS;
        ok[u] = t[u] < T;
    }
#pragma unroll
    for (int u = 0; u < AUNITS; u++)
        if (ok[u]) d[u] = dst[t[u] >> 2];
#pragma unroll
    for (int u = 0; u < AUNITS; u++)
        if (ok[u]) x[u] = es2[t[u]];
#pragma unroll
    for (int u = 0; u < AUNITS; u++)
        if (ok[u]) s[u] = g_so[d[u] * 4 + (t[u] & 3)];
#pragma unroll
    for (int u = 0; u < AUNITS; u++) {
        if (ok[u]) {
            float2 o;
            o.x = fmaf(x[u].x, s[u].x, s[u].y);
            o.y = fmaf(x[u].y, s[u].z, s[u].w);
            __stcs(&out2[t[u]], o);     // evict-first: don't displace es in L2
        }
    }
}

// -------- generic fallback (H != 8) ----------------------------------------
__global__ void accumG_kernel(const float* __restrict__ es,
                              const int*   __restrict__ dst, int E, int H)
{
    int e = blockIdx.x * blockDim.x + threadIdx.x;
    if (e >= E) return;
    int d = dst[e];
    float2* acc2 = reinterpret_cast<float2*>(g_acc);
    for (int h = 0; h < H; h++) {
        float x = es[e * H + h];
        atomicAdd(&acc2[d * 8 + h], make_float2(x, x * x));
    }
    atomicAdd(&g_cnt[d], 1.0f);
}

__global__ void statsG_kernel(const float* __restrict__ gain,
                              const float* __restrict__ bias, int H)
{
    int n = blockIdx.x * blockDim.x + threadIdx.x;
    if (n >= MAX_NODES) return;
    float rinv = 1.0f / fmaxf(g_cnt[n], 1.0f);
    float2* acc2 = reinterpret_cast<float2*>(g_acc);
    float2* so2  = reinterpret_cast<float2*>(g_so);
    for (int h = 0; h < H; h++) {
        float2 s = acc2[n * 8 + h];
        float m = s.x * rinv;
        float v = fmaxf(s.y - s.x * m, 0.f) * rinv;
        float iv = 1.0f / fmaxf(sqrtf(v), 1e-5f);
        float sc = gain[h] * iv;
        so2[n * 8 + h] = make_float2(sc, bias[h] - sc * m);
        acc2[n * 8 + h] = make_float2(0.f, 0.f);
    }
    g_cnt[n] = 0.f;
}

__global__ void applyG_kernel(const float* __restrict__ es,
                              const int*   __restrict__ dst,
                              float*       __restrict__ out, int E, int H)
{
    int e = blockIdx.x * blockDim.x + threadIdx.x;
    if (e >= E) return;
    int d = dst[e];
    float2* so2 = reinterpret_cast<float2*>(g_so);
    for (int h = 0; h < H; h++) {
        float2 s = so2[d * 8 + h];
        out[e * H + h] = fmaf(es[e * H + h], s.x, s.y);
    }
}

// ---------------------------------------------------------------------------
extern "C" void kernel_launch(void* const* d_in, const int* in_sizes, int n_in,
                              void* d_out, int out_size)
{
    const float* es   = (const float*)d_in[0];
    const float* gain = (const float*)d_in[1];
    const float* bias = (const float*)d_in[2];
    const int*   dst  = (const int*)  d_in[3];
    int E = in_sizes[3];
    int H = in_sizes[1];

    if (H == 8) {
        int T = 4 * E;                           // 4 lane-units per edge
        int span  = NTHREADS * UNITS;
        int aspan = NTHREADS * AUNITS;
        int tBlocks = (T + span - 1) / span;
        int aBlocks = (T + aspan - 1) / aspan;
        int sBlocks = (MAX_NODES * 4 + NTHREADS - 1) / NTHREADS;
        accum8_kernel<<<tBlocks, NTHREADS>>>((const float2*)es, dst, T);
        stats8_kernel<<<sBlocks, NTHREADS>>>(gain, bias);
        apply8_kernel<<<aBlocks, NTHREADS>>>((const float2*)es, dst,
                                             (float2*)d_out, T);
    } else {
        int nodeBlocks = (MAX_NODES + NTHREADS - 1) / NTHREADS;
        int edgeBlocks = (E + NTHREADS - 1) / NTHREADS;
        accumG_kernel<<<edgeBlocks, NTHREADS>>>(es, dst, E, H);
        statsG_kernel<<<nodeBlocks, NTHREADS>>>(gain, bias, H);
        applyG_kernel<<<edgeBlocks, NTHREADS>>>(es, dst, (float*)d_out, E, H);
    }
}

// round 13
// speedup vs baseline: 1.1455x; 1.1455x over previous
#include <cuda_runtime.h>
#include <cuda_bf16.h>

// ---------------------------------------------------------------------------
// EdgeNorm (one-pass moments), 4 lanes per edge (H==8), lane k owns heads
// {2k,2k+1}. float2 unit index == global thread-unit id (fully coalesced).
//
// Count elimination: lane 0 accumulates (x0 + CBIAS); count recovered in
// stats via rint(s.x/CBIAS). 4 LTS atomic ops per edge = structural floor.
//
// L2-residency plan (R10 layout — proven best): (scale,offset) written IN
// PLACE over the moments in g_acc, so apply gathers the same L2-hot lines
// accum's atomics created, and the working set
// (es 102.4 + dst 12.8 + acc 8.4 = 123.6MB) fits the 126MB L2. apply8 uses
// __stcs for output (evict-first; doesn't displace resident es) and
// reversed block order to start on accum's tail-hot lines. zero8 restores
// scratch after apply (replay-safe). Do NOT split scale/offset into a
// separate buffer or zero inside stats — measured 12us regression (R11).
// ---------------------------------------------------------------------------

#define MAX_NODES 131072
#define NTHREADS  256
#define UNITS     4
#define AUNITS    8
#define ZUNITS    4
#define CBIAS     128.0f
#define CBIAS_INV (1.0f / 128.0f)

__device__ float4 g_acc[MAX_NODES * 4];   // moments, then (scale,off) in place
__device__ float  g_cnt[MAX_NODES];       // fallback path only
__device__ float4 g_so [MAX_NODES * 4];   // fallback path only

// -------- H == 8 fast path -------------------------------------------------
__global__ void accum8_kernel(const float2* __restrict__ es2,
                              const int*    __restrict__ dst, int T)
{
    int base = blockIdx.x * (NTHREADS * UNITS) + threadIdx.x;
    int t[UNITS];
    bool ok[UNITS];
    int d[UNITS];
    float2 x[UNITS];
#pragma unroll
    for (int u = 0; u < UNITS; u++) {
        t[u] = base + u * NTHREADS;
        ok[u] = t[u] < T;
    }
#pragma unroll
    for (int u = 0; u < UNITS; u++)
        if (ok[u]) d[u] = dst[t[u] >> 2];
#pragma unroll
    for (int u = 0; u < UNITS; u++)
        if (ok[u]) x[u] = es2[t[u]];
#pragma unroll
    for (int u = 0; u < UNITS; u++) {
        if (ok[u]) {
            int k = t[u] & 3;
            float cb = (k == 0) ? CBIAS : 0.0f;   // count rides in lane 0's sum
            atomicAdd(&g_acc[d[u] * 4 + k],
                      make_float4(x[u].x + cb, x[u].x * x[u].x,
                                  x[u].y, x[u].y * x[u].y));
        }
    }
}

__global__ void stats8_kernel(const float* __restrict__ gain,
                              const float* __restrict__ bias)
{
    int t = blockIdx.x * blockDim.x + threadIdx.x;
    if (t >= MAX_NODES * 4) return;     // one thread per (node, head-pair)
    int k = t & 3;
    float4 s = g_acc[t];
    // lane-0 slot of this node sits in lane (lane & ~3) of the same warp:
    // broadcast its raw sum (carries CBIAS*count) via shuffle, no 2nd load.
    int lane = threadIdx.x & 31;
    float s0x = __shfl_sync(0xffffffffu, s.x, lane & ~3);
    float c = rintf(s0x * CBIAS_INV);
    if (k == 0) s.x = s.x - CBIAS * c;

    float rinv = 1.0f / fmaxf(c, 1.0f);
    float m0 = s.x * rinv;
    float v0 = fmaxf(s.y - s.x * m0, 0.f) * rinv;
    float sc0 = gain[2 * k + 0] / fmaxf(sqrtf(v0), 1e-5f);
    float of0 = bias[2 * k + 0] - sc0 * m0;
    float m1 = s.z * rinv;
    float v1 = fmaxf(s.w - s.z * m1, 0.f) * rinv;
    float sc1 = gain[2 * k + 1] / fmaxf(sqrtf(v1), 1e-5f);
    float of1 = bias[2 * k + 1] - sc1 * m1;
    g_acc[t] = make_float4(sc0, of0, sc1, of1);   // in place: keeps L2 set small
}

__global__ void apply8_kernel(const float2* __restrict__ es2,
                              const int*    __restrict__ dst,
                              float2*       __restrict__ out2, int T)
{
    // Reversed block order: read the es tail (still hot in L2 from accum) first.
    int rb = gridDim.x - 1 - blockIdx.x;
    int base = rb * (NTHREADS * AUNITS) + threadIdx.x;
    int t[AUNITS];
    bool ok[AUNITS];
    int d[AUNITS];
    float2 x[AUNITS];
    float4 s[AUNITS];
#pragma unroll
    for (int u = 0; u < AUNITS; u++) {
        t[u] = base + u * NTHREADS;
        ok[u] = t[u] < T;
    }
#pragma unroll
    for (int u = 0; u < AUNITS; u++)
        if (ok[u]) d[u] = dst[t[u] >> 2];
#pragma unroll
    for (int u = 0; u < AUNITS; u++)
        if (ok[u]) x[u] = es2[t[u]];
#pragma unroll
    for (int u = 0; u < AUNITS; u++)
        if (ok[u]) s[u] = g_acc[d[u] * 4 + (t[u] & 3)];
#pragma unroll
    for (int u = 0; u < AUNITS; u++) {
        if (ok[u]) {
            float2 o;
            o.x = fmaf(x[u].x, s[u].x, s[u].y);
            o.y = fmaf(x[u].y, s[u].z, s[u].w);
            __stcs(&out2[t[u]], o);     // evict-first: don't displace es in L2
        }
    }
}

__global__ void zero8_kernel()
{
    // 512 blocks x 256 threads x 4 coalesced STG.128 = 524288 float4 writes.
    int base = blockIdx.x * (NTHREADS * ZUNITS) + threadIdx.x;
    float4 z = make_float4(0.f, 0.f, 0.f, 0.f);
#pragma unroll
    for (int u = 0; u < ZUNITS; u++) {
        int i = base + u * NTHREADS;
        if (i < MAX_NODES * 4) g_acc[i] = z;
    }
}

// -------- generic fallback (H != 8) ----------------------------------------
__global__ void accumG_kernel(const float* __restrict__ es,
                              const int*   __restrict__ dst, int E, int H)
{
    int e = blockIdx.x * blockDim.x + threadIdx.x;
    if (e >= E) return;
    int d = dst[e];
    float2* acc2 = reinterpret_cast<float2*>(g_acc);
    for (int h = 0; h < H; h++) {
        float x = es[e * H + h];
        atomicAdd(&acc2[d * 8 + h], make_float2(x, x * x));
    }
    atomicAdd(&g_cnt[d], 1.0f);
}

__global__ void statsG_kernel(const float* __restrict__ gain,
                              const float* __restrict__ bias, int H)
{
    int n = blockIdx.x * blockDim.x + threadIdx.x;
    if (n >= MAX_NODES) return;
    float rinv = 1.0f / fmaxf(g_cnt[n], 1.0f);
    float2* acc2 = reinterpret_cast<float2*>(g_acc);
    float2* so2  = reinterpret_cast<float2*>(g_so);
    for (int h = 0; h < H; h++) {
        float2 s = acc2[n * 8 + h];
        float m = s.x * rinv;
        float v = fmaxf(s.y - s.x * m, 0.f) * rinv;
        float iv = 1.0f / fmaxf(sqrtf(v), 1e-5f);
        float sc = gain[h] * iv;
        so2[n * 8 + h] = make_float2(sc, bias[h] - sc * m);
        acc2[n * 8 + h] = make_float2(0.f, 0.f);
    }
    g_cnt[n] = 0.f;
}

__global__ void applyG_kernel(const float* __restrict__ es,
                              const int*   __restrict__ dst,
                              float*       __restrict__ out, int E, int H)
{
    int e = blockIdx.x * blockDim.x + threadIdx.x;
    if (e >= E) return;
    int d = dst[e];
    float2* so2 = reinterpret_cast<float2*>(g_so);
    for (int h = 0; h < H; h++) {
        float2 s = so2[d * 8 + h];
        out[e * H + h] = fmaf(es[e * H + h], s.x, s.y);
    }
}

// ---------------------------------------------------------------------------
extern "C" void kernel_launch(void* const* d_in, const int* in_sizes, int n_in,
                              void* d_out, int out_size)
{
    const float* es   = (const float*)d_in[0];
    const float* gain = (const float*)d_in[1];
    const float* bias = (const float*)d_in[2];
    const int*   dst  = (const int*)  d_in[3];
    int E = in_sizes[3];
    int H = in_sizes[1];

    if (H == 8) {
        int T = 4 * E;                           // 4 lane-units per edge
        int span  = NTHREADS * UNITS;
        int aspan = NTHREADS * AUNITS;
        int zspan = NTHREADS * ZUNITS;
        int tBlocks = (T + span - 1) / span;
        int aBlocks = (T + aspan - 1) / aspan;
        int sBlocks = (MAX_NODES * 4 + NTHREADS - 1) / NTHREADS;
        int zBlocks = (MAX_NODES * 4 + zspan - 1) / zspan;
        accum8_kernel<<<tBlocks, NTHREADS>>>((const float2*)es, dst, T);
        stats8_kernel<<<sBlocks, NTHREADS>>>(gain, bias);
        apply8_kernel<<<aBlocks, NTHREADS>>>((const float2*)es, dst,
                                             (float2*)d_out, T);
        zero8_kernel<<<zBlocks, NTHREADS>>>();   // scratch zero for next replay
    } else {
        int nodeBlocks = (MAX_NODES + NTHREADS - 1) / NTHREADS;
        int edgeBlocks = (E + NTHREADS - 1) / NTHREADS;
        accumG_kernel<<<edgeBlocks, NTHREADS>>>(es, dst, E, H);
        statsG_kernel<<<nodeBlocks, NTHREADS>>>(gain, bias, H);
        applyG_kernel<<<edgeBlocks, NTHREADS>>>(es, dst, (float*)d_out, E, H);
    }
}

// round 14
// speedup vs baseline: 1.1459x; 1.0004x over previous
#include <cuda_runtime.h>
#include <cuda_bf16.h>

// ---------------------------------------------------------------------------
// EdgeNorm (one-pass moments), 4 lanes per edge (H==8), lane k owns heads
// {2k,2k+1}. float2 unit index == global thread-unit id (fully coalesced).
//
// Count elimination: lane 0 accumulates (x0 + CBIAS); count recovered in
// stats via rint(s.x/CBIAS). 4 LTS atomic ops per edge = structural floor.
//
// L2-residency plan (R10 layout — proven best): (scale,offset) written IN
// PLACE over the moments in g_acc, so apply gathers the same L2-hot lines
// accum's atomics created, and the working set
// (es 102.4 + dst 12.8 + acc 8.4 = 123.6MB) fits the 126MB L2. apply8 uses
// __stcs for output (evict-first; doesn't displace resident es) and
// reversed block order to start on accum's tail-hot lines.
// Scratch restore for the next graph replay is a cudaMemsetAsync graph
// memset node (cheaper fixed cost than a zero kernel; R10/R12 measured the
// kernel variant at ~4.9us of almost pure launch overhead).
// Do NOT split scale/offset into a separate buffer or zero inside stats —
// measured 12us regression (R11: fresh dirty lines displace resident es).
// ---------------------------------------------------------------------------

#define MAX_NODES 131072
#define NTHREADS  256
#define UNITS     4
#define AUNITS    8
#define CBIAS     128.0f
#define CBIAS_INV (1.0f / 128.0f)

__device__ float4 g_acc[MAX_NODES * 4];   // moments, then (scale,off) in place
__device__ float  g_cnt[MAX_NODES];       // fallback path only
__device__ float4 g_so [MAX_NODES * 4];   // fallback path only

// -------- H == 8 fast path -------------------------------------------------
__global__ void accum8_kernel(const float2* __restrict__ es2,
                              const int*    __restrict__ dst, int T)
{
    int base = blockIdx.x * (NTHREADS * UNITS) + threadIdx.x;
    int t[UNITS];
    bool ok[UNITS];
    int d[UNITS];
    float2 x[UNITS];
#pragma unroll
    for (int u = 0; u < UNITS; u++) {
        t[u] = base + u * NTHREADS;
        ok[u] = t[u] < T;
    }
#pragma unroll
    for (int u = 0; u < UNITS; u++)
        if (ok[u]) d[u] = dst[t[u] >> 2];
#pragma unroll
    for (int u = 0; u < UNITS; u++)
        if (ok[u]) x[u] = es2[t[u]];
#pragma unroll
    for (int u = 0; u < UNITS; u++) {
        if (ok[u]) {
            int k = t[u] & 3;
            float cb = (k == 0) ? CBIAS : 0.0f;   // count rides in lane 0's sum
            atomicAdd(&g_acc[d[u] * 4 + k],
                      make_float4(x[u].x + cb, x[u].x * x[u].x,
                                  x[u].y, x[u].y * x[u].y));
        }
    }
}

__global__ void stats8_kernel(const float* __restrict__ gain,
                              const float* __restrict__ bias)
{
    int t = blockIdx.x * blockDim.x + threadIdx.x;
    if (t >= MAX_NODES * 4) return;     // one thread per (node, head-pair)
    int k = t & 3;
    float4 s = g_acc[t];
    // lane-0 slot of this node sits in lane (lane & ~3) of the same warp:
    // broadcast its raw sum (carries CBIAS*count) via shuffle, no 2nd load.
    int lane = threadIdx.x & 31;
    float s0x = __shfl_sync(0xffffffffu, s.x, lane & ~3);
    float c = rintf(s0x * CBIAS_INV);
    if (k == 0) s.x = s.x - CBIAS * c;

    float rinv = 1.0f / fmaxf(c, 1.0f);
    float m0 = s.x * rinv;
    float v0 = fmaxf(s.y - s.x * m0, 0.f) * rinv;
    float sc0 = gain[2 * k + 0] / fmaxf(sqrtf(v0), 1e-5f);
    float of0 = bias[2 * k + 0] - sc0 * m0;
    float m1 = s.z * rinv;
    float v1 = fmaxf(s.w - s.z * m1, 0.f) * rinv;
    float sc1 = gain[2 * k + 1] / fmaxf(sqrtf(v1), 1e-5f);
    float of1 = bias[2 * k + 1] - sc1 * m1;
    g_acc[t] = make_float4(sc0, of0, sc1, of1);   // in place: keeps L2 set small
}

__global__ void apply8_kernel(const float2* __restrict__ es2,
                              const int*    __restrict__ dst,
                              float2*       __restrict__ out2, int T)
{
    // Reversed block order: read the es tail (still hot in L2 from accum) first.
    int rb = gridDim.x - 1 - blockIdx.x;
    int base = rb * (NTHREADS * AUNITS) + threadIdx.x;
    int t[AUNITS];
    bool ok[AUNITS];
    int d[AUNITS];
    float2 x[AUNITS];
    float4 s[AUNITS];
#pragma unroll
    for (int u = 0; u < AUNITS; u++) {
        t[u] = base + u * NTHREADS;
        ok[u] = t[u] < T;
    }
#pragma unroll
    for (int u = 0; u < AUNITS; u++)
        if (ok[u]) d[u] = dst[t[u] >> 2];
#pragma unroll
    for (int u = 0; u < AUNITS; u++)
        if (ok[u]) x[u] = es2[t[u]];
#pragma unroll
    for (int u = 0; u < AUNITS; u++)
        if (ok[u]) s[u] = g_acc[d[u] * 4 + (t[u] & 3)];
#pragma unroll
    for (int u = 0; u < AUNITS; u++) {
        if (ok[u]) {
            float2 o;
            o.x = fmaf(x[u].x, s[u].x, s[u].y);
            o.y = fmaf(x[u].y, s[u].z, s[u].w);
            __stcs(&out2[t[u]], o);     // evict-first: don't displace es in L2
        }
    }
}

// -------- generic fallback (H != 8) ----------------------------------------
__global__ void accumG_kernel(const float* __restrict__ es,
                              const int*   __restrict__ dst, int E, int H)
{
    int e = blockIdx.x * blockDim.x + threadIdx.x;
    if (e >= E) return;
    int d = dst[e];
    float2* acc2 = reinterpret_cast<float2*>(g_acc);
    for (int h = 0; h < H; h++) {
        float x = es[e * H + h];
        atomicAdd(&acc2[d * 8 + h], make_float2(x, x * x));
    }
    atomicAdd(&g_cnt[d], 1.0f);
}

__global__ void statsG_kernel(const float* __restrict__ gain,
                              const float* __restrict__ bias, int H)
{
    int n = blockIdx.x * blockDim.x + threadIdx.x;
    if (n >= MAX_NODES) return;
    float rinv = 1.0f / fmaxf(g_cnt[n], 1.0f);
    float2* acc2 = reinterpret_cast<float2*>(g_acc);
    float2* so2  = reinterpret_cast<float2*>(g_so);
    for (int h = 0; h < H; h++) {
        float2 s = acc2[n * 8 + h];
        float m = s.x * rinv;
        float v = fmaxf(s.y - s.x * m, 0.f) * rinv;
        float iv = 1.0f / fmaxf(sqrtf(v), 1e-5f);
        float sc = gain[h] * iv;
        so2[n * 8 + h] = make_float2(sc, bias[h] - sc * m);
        acc2[n * 8 + h] = make_float2(0.f, 0.f);
    }
    g_cnt[n] = 0.f;
}

__global__ void applyG_kernel(const float* __restrict__ es,
                              const int*   __restrict__ dst,
                              float*       __restrict__ out, int E, int H)
{
    int e = blockIdx.x * blockDim.x + threadIdx.x;
    if (e >= E) return;
    int d = dst[e];
    float2* so2 = reinterpret_cast<float2*>(g_so);
    for (int h = 0; h < H; h++) {
        float2 s = so2[d * 8 + h];
        out[e * H + h] = fmaf(es[e * H + h], s.x, s.y);
    }
}

// ---------------------------------------------------------------------------
extern "C" void kernel_launch(void* const* d_in, const int* in_sizes, int n_in,
                              void* d_out, int out_size)
{
    const float* es   = (const float*)d_in[0];
    const float* gain = (const float*)d_in[1];
    const float* bias = (const float*)d_in[2];
    const int*   dst  = (const int*)  d_in[3];
    int E = in_sizes[3];
    int H = in_sizes[1];

    if (H == 8) {
        int T = 4 * E;                           // 4 lane-units per edge
        int span  = NTHREADS * UNITS;
        int aspan = NTHREADS * AUNITS;
        int tBlocks = (T + span - 1) / span;
        int aBlocks = (T + aspan - 1) / aspan;
        int sBlocks = (MAX_NODES * 4 + NTHREADS - 1) / NTHREADS;
        accum8_kernel<<<tBlocks, NTHREADS>>>((const float2*)es, dst, T);
        stats8_kernel<<<sBlocks, NTHREADS>>>(gain, bias);
        apply8_kernel<<<aBlocks, NTHREADS>>>((const float2*)es, dst,
                                             (float2*)d_out, T);
        // Scratch restore for next replay: graph memset node (no kernel
        // launch overhead). Ordered after apply on the same stream.
        void* accPtr = nullptr;
        cudaGetSymbolAddress(&accPtr, g_acc);
        cudaMemsetAsync(accPtr, 0, sizeof(float4) * MAX_NODES * 4, 0);
    } else {
        int nodeBlocks = (MAX_NODES + NTHREADS - 1) / NTHREADS;
        int edgeBlocks = (E + NTHREADS - 1) / NTHREADS;
        accumG_kernel<<<edgeBlocks, NTHREADS>>>(es, dst, E, H);
        statsG_kernel<<<nodeBlocks, NTHREADS>>>(gain, bias, H);
        applyG_kernel<<<edgeBlocks, NTHREADS>>>(es, dst, (float*)d_out, E, H);
    }
}